// round 8
// baseline (speedup 1.0000x reference)
#include <cuda_runtime.h>
#include <cuda_bf16.h>
#include <cstdint>

// Problem constants
#define BATCH 32
#define CIN   256
#define COUT  256
#define Hh    56
#define Ww    56
#define NPIX  (Hh*Ww)          // 3136
#define QDIM  3364             // 58*58 padded pixels per image
#define QPAD  4096             // padded + guard rows per image
#define GOFF  64               // guard offset (rows before q=0)
#define NVALS 100352.0
#define BN_EPS 1e-5

// GEMM config
#define NCHUNK 72              // K = 9 taps * 256 ci ; 72 chunks of k32
#define ROWB   48              // smem row stride (bytes) for 32B k-chunk rows
#define STAGEB (128*ROWB*2)    // A[128][48] + B[128][48] = 12288 B
#define NSTAGE 3               // static 36 KB; prefetch distance 2 -> no collision

// ----------------- device scratch -----------------
__device__ __align__(256) char  g_xs[(size_t)BATCH * QPAD * CIN];   // 33.5 MB [b][qq][ci] s8
__device__ __align__(256) char  g_ws[9 * COUT * CIN];               // 0.59 MB [tap][co][ci] s8
__device__ float              g_alpha[COUT];
__device__ int                g_sum[COUT];
__device__ unsigned long long g_sumsq[COUT];
__device__ float              g_scale[COUT];
__device__ float              g_shift[COUT];
__device__ __align__(256) short g_S[(size_t)BATCH * NPIX * COUT];   // 51.4 MB [b][p][co]

// ----------------- helpers -----------------
__device__ __forceinline__ uint32_t smem_u32(const void* p) {
    uint32_t a;
    asm("{ .reg .u64 t; cvta.to.shared.u64 t, %1; cvt.u32.u64 %0, t; }" : "=r"(a) : "l"(p));
    return a;
}
__device__ __forceinline__ void cpasync16(uint32_t dst, const void* src) {
    asm volatile("cp.async.cg.shared.global [%0], [%1], 16;" :: "r"(dst), "l"(src) : "memory");
}
__device__ __forceinline__ void mma_s8(int* d, const unsigned* a, const unsigned* b) {
    asm volatile(
        "mma.sync.aligned.m16n8k32.row.col.s32.s8.s8.s32 "
        "{%0,%1,%2,%3}, {%4,%5,%6,%7}, {%8,%9}, {%0,%1,%2,%3};"
        : "+r"(d[0]), "+r"(d[1]), "+r"(d[2]), "+r"(d[3])
        : "r"(a[0]), "r"(a[1]), "r"(a[2]), "r"(a[3]), "r"(b[0]), "r"(b[1]));
}

// ----------------- kernel 1: zero stats -----------------
__global__ void zero_stats_kernel() {
    int t = threadIdx.x;
    if (t < COUT) { g_sum[t] = 0; g_sumsq[t] = 0ull; }
}

// ----------------- kernel 2: zero x buffer -----------------
__global__ void __launch_bounds__(256) zero_xs_kernel() {
    size_t n = (size_t)BATCH * QPAD * CIN / 16;
    uint4* p = (uint4*)g_xs;
    uint4 z = make_uint4(0, 0, 0, 0);
    for (size_t i = (size_t)blockIdx.x * 256 + threadIdx.x; i < n; i += (size_t)gridDim.x * 256) p[i] = z;
}

// ----------------- kernel 3: weight prep (alpha + s8 signs) -----------------
__global__ void __launch_bounds__(256) prep_w_kernel(const float* __restrict__ w) {
    int co = blockIdx.x;
    int ci = threadIdx.x;
    int lane = ci & 31, warp = ci >> 5;

    float v[9];
    const float* wp = w + ((size_t)co * CIN + ci) * 9;
#pragma unroll
    for (int t = 0; t < 9; t++) v[t] = wp[t];

    __shared__ float part[8][9];
    __shared__ float tapmean[9];
#pragma unroll
    for (int t = 0; t < 9; t++) {
        float s = v[t];
#pragma unroll
        for (int o = 16; o > 0; o >>= 1) s += __shfl_down_sync(0xffffffffu, s, o);
        if (lane == 0) part[warp][t] = s;
    }
    __syncthreads();
    if (ci < 9) {
        float s = 0.f;
#pragma unroll
        for (int i = 0; i < 8; i++) s += part[i][ci];
        tapmean[ci] = s * (1.0f / 256.0f);
    }
    __syncthreads();

    float asum = 0.f;
#pragma unroll
    for (int t = 0; t < 9; t++) {
        float wc = v[t] - tapmean[t];
        wc = fminf(fmaxf(wc, -1.0f), 1.0f);
        asum += fabsf(wc);
        int sg = (wc > 0.f) - (wc < 0.f);
        g_ws[((size_t)t * COUT + co) * CIN + ci] = (char)sg;
    }
    __syncthreads();
#pragma unroll
    for (int o = 16; o > 0; o >>= 1) asum += __shfl_down_sync(0xffffffffu, asum, o);
    if (lane == 0) part[warp][0] = asum;
    __syncthreads();
    if (ci == 0) {
        float tot = 0.f;
#pragma unroll
        for (int i = 0; i < 8; i++) tot += part[i][0];
        g_alpha[co] = tot * (1.0f / 2304.0f);
    }
}

// ----------------- kernel 4: binarize x -> g_xs[b][qq][ci] s8 -----------------
__global__ void __launch_bounds__(256) fill_xs_kernel(const float* __restrict__ x) {
    int h = blockIdx.x, b = blockIdx.y;
    int tid = threadIdx.x;
    __shared__ char s[CIN][Ww];

    for (int idx = tid; idx < CIN * Ww; idx += 256) {
        int ci = idx / Ww, w = idx % Ww;
        float v = x[((size_t)(b * CIN + ci)) * NPIX + h * Ww + w];
        s[ci][w] = (char)((v > 0.f) - (v < 0.f));
    }
    __syncthreads();
    for (int idx = tid; idx < Ww * 64; idx += 256) {
        int w = idx >> 6, c4 = idx & 63;
        char4 pk = make_char4(s[4*c4][w], s[4*c4+1][w], s[4*c4+2][w], s[4*c4+3][w]);
        size_t qq = (size_t)b * QPAD + GOFF + (h + 1) * 58 + (w + 1);
        *(char4*)(g_xs + qq * 256 + 4 * c4) = pk;
    }
}

// ----------------- kernel 5: int8 mma.sync implicit-GEMM conv + fused epilogue -----------------
__global__ void __launch_bounds__(256, 1) conv_mma_kernel() {
    __shared__ __align__(128) char sm[NSTAGE * STAGEB];    // 36 KB static
    __shared__ int s_sum[128];
    __shared__ int s_sq[128];

    int tid = threadIdx.x, wid = tid >> 5, lane = tid & 31;
    int mwarp = wid & 3;            // 0..3 -> 32 q-rows each
    int nwarp = wid >> 2;           // 0..1 -> 64 couts each
    int n0 = blockIdx.x * 128;
    int q0 = blockIdx.y * 128;
    int b  = blockIdx.z;

    if (tid < 128) { s_sum[tid] = 0; s_sq[tid] = 0; }

    uint32_t sb = smem_u32(sm);
    const char* gx = g_xs + ((size_t)b * QPAD + GOFF) * 256;
    const char* gw = g_ws;

    int crow = tid >> 1, chalf = tid & 1;      // copy assignment: 128 rows x 2 halves

    auto issue_copy = [&](int c) {
        int tap = c >> 3, ci0 = (c & 7) << 5;
        int st = c % NSTAGE;
        int off = (tap / 3 - 1) * 58 + (tap % 3) - 1;
        uint32_t abase = sb + st * STAGEB;
        cpasync16(abase + crow * ROWB + chalf * 16,
                  gx + ((size_t)(q0 + off + crow)) * 256 + ci0 + chalf * 16);
        cpasync16(abase + 128 * ROWB + crow * ROWB + chalf * 16,
                  gw + ((size_t)(tap * COUT + n0 + crow)) * 256 + ci0 + chalf * 16);
        asm volatile("cp.async.commit_group;" ::: "memory");
    };

    int d[2][8][4];
#pragma unroll
    for (int mf = 0; mf < 2; mf++)
#pragma unroll
        for (int nf = 0; nf < 8; nf++)
#pragma unroll
            for (int j = 0; j < 4; j++) d[mf][nf][j] = 0;

    issue_copy(0); issue_copy(1);

    for (int k = 0; k < NCHUNK; k++) {
        if (k < NCHUNK - 1) asm volatile("cp.async.wait_group 1;" ::: "memory");
        else                asm volatile("cp.async.wait_group 0;" ::: "memory");
        __syncthreads();    // single barrier per chunk

        const char* stg = sm + (k % NSTAGE) * STAGEB;
        // A fragments (warp rows mwarp*32 .. +32, two m16 blocks)
        unsigned a[2][4];
        {
            int r = mwarp * 32 + (lane >> 2);
            int cb = (lane & 3) * 4;
#pragma unroll
            for (int mf = 0; mf < 2; mf++) {
                const char* base = stg + (size_t)(r + mf * 16) * ROWB + cb;
                a[mf][0] = *(const unsigned*)(base);
                a[mf][1] = *(const unsigned*)(base + 8 * ROWB);
                a[mf][2] = *(const unsigned*)(base + 16);
                a[mf][3] = *(const unsigned*)(base + 8 * ROWB + 16);
            }
        }
        // B fragments (warp cols nwarp*64 .. +64, eight n8 blocks)
        unsigned bf[8][2];
        {
            int nrb = nwarp * 64 + (lane >> 2);
            int cb = (lane & 3) * 4;
#pragma unroll
            for (int nf = 0; nf < 8; nf++) {
                const char* base = stg + (size_t)(128 * ROWB) + (size_t)(nrb + nf * 8) * ROWB + cb;
                bf[nf][0] = *(const unsigned*)(base);
                bf[nf][1] = *(const unsigned*)(base + 16);
            }
        }
        // Prefetch into stage (k+2)%3 (!= k%3); its previous contents were read
        // in iteration k-1 and all warps are past this iteration's barrier.
        if (k + 2 < NCHUNK) issue_copy(k + 2);

#pragma unroll
        for (int mf = 0; mf < 2; mf++)
#pragma unroll
            for (int nf = 0; nf < 8; nf++)
                mma_s8(d[mf][nf], a[mf], bf[nf]);
    }

    // ---- epilogue: S store + channel stats ----
    int qb = q0 + mwarp * 32 + (lane >> 2);
    int cpair = (lane & 3) * 2;

#pragma unroll
    for (int nf = 0; nf < 8; nf++) {
        int co = n0 + nwarp * 64 + nf * 8 + cpair;
        int fs0 = 0, fs1 = 0, fq0 = 0, fq1 = 0;
#pragma unroll
        for (int mf = 0; mf < 2; mf++) {
#pragma unroll
            for (int rs = 0; rs < 2; rs++) {
                int q = qb + mf * 16 + rs * 8;
                int r = q / 58, cc = q % 58;
                bool valid = (q < QDIM) && (r >= 1) && (r <= Hh) && (cc >= 1) && (cc <= Ww);
                int v0 = d[mf][nf][rs * 2];
                int v1 = d[mf][nf][rs * 2 + 1];
                if (valid) {
                    int p = (r - 1) * Ww + (cc - 1);
                    unsigned pk = (unsigned)(unsigned short)(short)v0 |
                                  ((unsigned)(unsigned short)(short)v1 << 16);
                    *(unsigned*)(g_S + ((size_t)(b * NPIX) + p) * COUT + co) = pk;
                    fs0 += v0; fs1 += v1;
                    fq0 += v0 * v0; fq1 += v1 * v1;
                }
            }
        }
#pragma unroll
        for (int o = 4; o <= 16; o <<= 1) {
            fs0 += __shfl_xor_sync(0xffffffffu, fs0, o);
            fs1 += __shfl_xor_sync(0xffffffffu, fs1, o);
            fq0 += __shfl_xor_sync(0xffffffffu, fq0, o);
            fq1 += __shfl_xor_sync(0xffffffffu, fq1, o);
        }
        if (lane < 4) {
            int cl = nwarp * 64 + nf * 8 + cpair;
            atomicAdd(&s_sum[cl], fs0);
            atomicAdd(&s_sum[cl + 1], fs1);
            atomicAdd(&s_sq[cl], fq0);
            atomicAdd(&s_sq[cl + 1], fq1);
        }
    }
    __syncthreads();
    if (tid < 128) {
        atomicAdd(&g_sum[n0 + tid], s_sum[tid]);
        atomicAdd(&g_sumsq[n0 + tid], (unsigned long long)(long long)s_sq[tid]);
    }
}

// ----------------- kernel 6: finalize thresholds -----------------
__global__ void finalize_kernel(const float* __restrict__ gamma,
                                const float* __restrict__ beta) {
    int co = threadIdx.x;
    if (co >= COUT) return;
    double s    = (double)g_sum[co];
    double sq   = (double)(long long)g_sumsq[co];
    double mean = s / NVALS;
    double var  = sq / NVALS - mean * mean;
    double a    = (double)g_alpha[co];
    double inv  = 1.0 / sqrt(a * a * var + BN_EPS);
    double sc   = (double)gamma[co] * a * inv;
    g_scale[co] = (float)sc;
    g_shift[co] = (float)((double)beta[co] - sc * mean);
}

// ----------------- kernel 7: threshold + transpose -----------------
__global__ void __launch_bounds__(256) thresh_kernel(float* __restrict__ out) {
    __shared__ float tile[32][33];
    int p0  = blockIdx.x * 32;
    int co0 = blockIdx.y * 32;
    int b   = blockIdx.z;
    int tx  = threadIdx.x, ty = threadIdx.y;

    float sc = g_scale[co0 + tx];
    float sh = g_shift[co0 + tx];
#pragma unroll
    for (int r = 0; r < 4; r++) {
        int pl = ty * 4 + r;
        short s = g_S[((size_t)(b * NPIX + p0 + pl)) * COUT + co0 + tx];
        tile[pl][tx] = (fmaf(sc, (float)s, sh) > 0.0f) ? 1.0f : 0.0f;
    }
    __syncthreads();
#pragma unroll
    for (int r = 0; r < 4; r++) {
        int cl = ty * 4 + r;
        out[((size_t)(b * COUT + co0 + cl)) * NPIX + p0 + tx] = tile[tx][cl];
    }
}

// ----------------- launch -----------------
extern "C" void kernel_launch(void* const* d_in, const int* in_sizes, int n_in,
                              void* d_out, int out_size) {
    const float* x      = (const float*)d_in[0];
    const float* weight = (const float*)d_in[1];
    // bias (d_in[2]) cancels inside training-mode BN
    const float* gamma  = (const float*)d_in[3];
    const float* beta   = (const float*)d_in[4];
    float* out = (float*)d_out;

    zero_stats_kernel<<<1, 256>>>();
    zero_xs_kernel<<<2048, 256>>>();
    prep_w_kernel<<<COUT, 256>>>(weight);
    fill_xs_kernel<<<dim3(Hh, BATCH), 256>>>(x);
    conv_mma_kernel<<<dim3(2, 27, BATCH), 256>>>();
    finalize_kernel<<<1, 256>>>(gamma, beta);
    thresh_kernel<<<dim3(NPIX / 32, COUT / 32, BATCH), dim3(32, 8)>>>(out);
}

// round 9
// speedup vs baseline: 3.5145x; 3.5145x over previous
#include <cuda_runtime.h>
#include <cuda_bf16.h>
#include <cstdint>

// Problem constants
#define BATCH 32
#define CIN   256
#define COUT  256
#define Hh    56
#define Ww    56
#define NPIX  (Hh*Ww)          // 3136
#define CW    8                // 256 bits = 8 x uint32 words per pixel
#define NVALS 100352.0         // BATCH*NPIX per-channel count
#define BN_EPS 1e-5

// ----------------- scratch (device globals; no allocation) -----------------
__device__ unsigned           g_xbits[BATCH * NPIX * CW];       // [b][p][wd]  3.2 MB
__device__ unsigned           g_wbits[COUT * 9 * CW];           // [co][tap][wd]
__device__ float              g_alpha[COUT];
__device__ int                g_sum[COUT];
__device__ unsigned long long g_sumsq[COUT];
__device__ float              g_scale[COUT];
__device__ float              g_shift[COUT];
__device__ short              g_S[BATCH * NPIX * COUT];         // [b][p][co] 51.4 MB

// ----------------- kernel 1: zero the stats accumulators -----------------
__global__ void zero_stats_kernel() {
    int t = threadIdx.x;
    if (t < COUT) { g_sum[t] = 0; g_sumsq[t] = 0ull; }
}

// ----------------- kernel 2: weight prep -----------------
// Per co: mean over C_in per tap, clamp, alpha = mean|wc|, sign bits (bit=1 <=> negative).
__global__ void __launch_bounds__(256) prep_w_kernel(const float* __restrict__ w) {
    int co   = blockIdx.x;
    int ci   = threadIdx.x;           // 0..255
    int lane = ci & 31;
    int warp = ci >> 5;               // = word index (ci/32)

    float v[9];
    const float* wp = w + ((size_t)co * CIN + ci) * 9;
#pragma unroll
    for (int t = 0; t < 9; t++) v[t] = wp[t];

    __shared__ float part[8][9];
    __shared__ float tapmean[9];

#pragma unroll
    for (int t = 0; t < 9; t++) {
        float s = v[t];
#pragma unroll
        for (int o = 16; o > 0; o >>= 1) s += __shfl_down_sync(0xffffffffu, s, o);
        if (lane == 0) part[warp][t] = s;
    }
    __syncthreads();
    if (ci < 9) {
        float s = 0.f;
#pragma unroll
        for (int i = 0; i < 8; i++) s += part[i][ci];
        tapmean[ci] = s * (1.0f / 256.0f);
    }
    __syncthreads();

    float asum = 0.f;
#pragma unroll
    for (int t = 0; t < 9; t++) {
        float wc = v[t] - tapmean[t];
        wc = fminf(fmaxf(wc, -1.0f), 1.0f);
        asum += fabsf(wc);
        unsigned m = __ballot_sync(0xffffffffu, wc < 0.0f);
        if (lane == 0) g_wbits[co * 72 + t * CW + warp] = m;
    }
    __syncthreads();
#pragma unroll
    for (int o = 16; o > 0; o >>= 1) asum += __shfl_down_sync(0xffffffffu, asum, o);
    if (lane == 0) part[warp][0] = asum;
    __syncthreads();
    if (ci == 0) {
        float tot = 0.f;
#pragma unroll
        for (int i = 0; i < 8; i++) tot += part[i][0];
        g_alpha[co] = tot * (1.0f / 2304.0f);
    }
}

// ----------------- kernel 3: binarize x into bit-planes -----------------
__global__ void __launch_bounds__(256) binarize_kernel(const float* __restrict__ x) {
    int idx = blockIdx.x * 256 + threadIdx.x;       // 0 .. BATCH*CW*NPIX-1
    if (idx >= BATCH * CW * NPIX) return;
    int p  = idx % NPIX;
    int wd = (idx / NPIX) % CW;
    int b  = idx / (NPIX * CW);

    const float* xp = x + ((size_t)(b * CIN + wd * 32) * NPIX) + p;
    unsigned m = 0u;
#pragma unroll
    for (int k = 0; k < 32; k++) {
        float v = xp[(size_t)k * NPIX];
        m |= (v < 0.0f ? 1u : 0u) << k;
    }
    g_xbits[((size_t)(b * NPIX + p)) * CW + wd] = m;
}

// ----------------- kernel 4: XNOR-popcount conv, lane-pair split over ci -----------------
// Block = (h, b), 512 threads. Thread (2i, 2i+1) handle cout i, ci halves [0,128) / [128,256).
// Each half computes S_half = 128*nvalid - 2*P_half + 2*corr_half; halves combine via shfl.
__global__ void __launch_bounds__(512) conv_kernel() {
    int h   = blockIdx.x;      // 0..55
    int b   = blockIdx.y;      // 0..31
    int tid = threadIdx.x;     // 0..511
    int co   = tid >> 1;       // 0..255
    int half = tid & 1;        // 0 = words 0-3, 1 = words 4-7
    int lane = tid & 31;

    __shared__ unsigned sx[3][Ww + 2][CW];    // 5.57 KB, zero-padded cols 0 and 57

    // zero everything (covers pad cols + invalid rows)
    for (int i = tid; i < 3 * (Ww + 2) * CW; i += 512) ((unsigned*)sx)[i] = 0u;
    __syncthreads();
#pragma unroll
    for (int r = 0; r < 3; r++) {
        int gh = h - 1 + r;
        if (gh >= 0 && gh < Hh) {
            const unsigned* src = g_xbits + ((size_t)(b * NPIX + gh * Ww)) * CW;
            unsigned* dst = &sx[r][1][0];
            for (int i = tid; i < Ww * CW; i += 512) dst[i] = src[i];
        }
    }
    __syncthreads();

    // per-thread weights: 9 taps x 4 words (this half)
    unsigned wreg[36];
    {
        const unsigned* wp = g_wbits + co * 72 + half * 4;
#pragma unroll
        for (int t = 0; t < 9; t++) {
            uint4 q = *(const uint4*)(wp + t * CW);
            wreg[t * 4 + 0] = q.x; wreg[t * 4 + 1] = q.y;
            wreg[t * 4 + 2] = q.z; wreg[t * 4 + 3] = q.w;
        }
    }
    // per-tap weight popcounts (this half) for border corrections
    int nw[9];
#pragma unroll
    for (int t = 0; t < 9; t++)
        nw[t] = __popc(wreg[t*4]) + __popc(wreg[t*4+1]) + __popc(wreg[t*4+2]) + __popc(wreg[t*4+3]);

    int rowInv = (h == 0) ? 0 : (h == Hh - 1) ? 2 : -1;
    int corrH = 0, nvH = 9;
    if (rowInv >= 0) { corrH = nw[rowInv*3+0] + nw[rowInv*3+1] + nw[rowInv*3+2]; nvH = 6; }
    int nwc0 = nw[0] + nw[3] + nw[6];
    int nwc2 = nw[2] + nw[5] + nw[8];
    int rflag = (rowInv >= 0) ? 1 : 0;

    short* sout = g_S + ((size_t)(b * NPIX) + h * Ww) * COUT + co;
    int lsum = 0, lsq = 0;

#pragma unroll 2
    for (int w = 0; w < Ww; w++) {
        int P = 0;
#pragma unroll
        for (int t = 0; t < 9; t++) {
            int r = t / 3, c = t % 3;
            uint4 xa = *(const uint4*)(&sx[r][w + c][half * 4]);
            P += __popc(xa.x ^ wreg[t*4+0]) + __popc(xa.y ^ wreg[t*4+1]);
            P += __popc(xa.z ^ wreg[t*4+2]) + __popc(xa.w ^ wreg[t*4+3]);
        }
        int nvalid = nvH, corr = corrH;
        if (w == 0) {
            nvalid = nvH - 3 + rflag;
            corr   = corrH + nwc0 - (rflag ? nw[rowInv*3+0] : 0);
        } else if (w == Ww - 1) {
            nvalid = nvH - 3 + rflag;
            corr   = corrH + nwc2 - (rflag ? nw[rowInv*3+2] : 0);
        }
        int Sh = 128 * nvalid - 2 * P + 2 * corr;      // half contribution
        int S  = Sh + __shfl_xor_sync(0xffffffffu, Sh, 1);
        if (half == 0) {
            sout[(size_t)w * COUT] = (short)S;
            lsum += S;
            lsq  += S * S;        // <= 56*2304^2 = 2.97e8 < INT_MAX
        }
    }
    if (half == 0) {
        atomicAdd(&g_sum[co], lsum);
        atomicAdd(&g_sumsq[co], (unsigned long long)(long long)lsq);
    }
    (void)lane;
}

// ----------------- kernel 5: finalize per-channel thresholds -----------------
__global__ void finalize_kernel(const float* __restrict__ gamma,
                                const float* __restrict__ beta) {
    int co = threadIdx.x;
    if (co >= COUT) return;
    double s    = (double)g_sum[co];
    double sq   = (double)(long long)g_sumsq[co];
    double mean = s / NVALS;
    double var  = sq / NVALS - mean * mean;            // exact var of integer S
    double a    = (double)g_alpha[co];
    double inv  = 1.0 / sqrt(a * a * var + BN_EPS);
    double sc   = (double)gamma[co] * a * inv;
    g_scale[co] = (float)sc;
    g_shift[co] = (float)((double)beta[co] - sc * mean);
}

// ----------------- kernel 6: threshold + transpose [b][p][co] -> [b][co][p] -----------------
__global__ void __launch_bounds__(256) thresh_kernel(float* __restrict__ out) {
    __shared__ float tile[32][33];
    int p0  = blockIdx.x * 32;     // 98 tiles (3136 = 98*32)
    int co0 = blockIdx.y * 32;     // 8 tiles
    int b   = blockIdx.z;
    int tx  = threadIdx.x;         // 0..31
    int ty  = threadIdx.y;         // 0..7

    float sc = g_scale[co0 + tx];
    float sh = g_shift[co0 + tx];
#pragma unroll
    for (int r = 0; r < 4; r++) {
        int pl = ty * 4 + r;
        short s = g_S[((size_t)(b * NPIX + p0 + pl)) * COUT + co0 + tx];
        tile[pl][tx] = (fmaf(sc, (float)s, sh) > 0.0f) ? 1.0f : 0.0f;
    }
    __syncthreads();
#pragma unroll
    for (int r = 0; r < 4; r++) {
        int cl = ty * 4 + r;
        out[((size_t)(b * COUT + co0 + cl)) * NPIX + p0 + tx] = tile[tx][cl];
    }
}

// ----------------- launch -----------------
extern "C" void kernel_launch(void* const* d_in, const int* in_sizes, int n_in,
                              void* d_out, int out_size) {
    const float* x      = (const float*)d_in[0];
    const float* weight = (const float*)d_in[1];
    // const float* bias = (const float*)d_in[2];  // cancels inside BN; unused
    const float* gamma  = (const float*)d_in[3];
    const float* beta   = (const float*)d_in[4];
    float* out = (float*)d_out;

    zero_stats_kernel<<<1, 256>>>();
    prep_w_kernel<<<COUT, 256>>>(weight);
    {
        int nwords = BATCH * CW * NPIX;
        binarize_kernel<<<(nwords + 255) / 256, 256>>>(x);
    }
    conv_kernel<<<dim3(Hh, BATCH), 512>>>();
    finalize_kernel<<<1, 256>>>(gamma, beta);
    thresh_kernel<<<dim3(NPIX / 32, COUT / 32, BATCH), dim3(32, 8)>>>(out);
}

// round 10
// speedup vs baseline: 3.7663x; 1.0717x over previous
#include <cuda_runtime.h>
#include <cuda_bf16.h>
#include <cstdint>

// Problem constants
#define BATCH 32
#define CIN   256
#define COUT  256
#define Hh    56
#define Ww    56
#define NPIX  (Hh*Ww)          // 3136
#define CW    8                // 256 bits = 8 x uint32 words per pixel
#define NVALS 100352.0         // BATCH*NPIX per-channel count
#define BN_EPS 1e-5

// ----------------- scratch (device globals; no allocation) -----------------
__device__ unsigned           g_xbits[BATCH * NPIX * CW];       // [b][p][wd]  3.2 MB
__device__ unsigned           g_wbits[COUT * 9 * CW];           // [co][tap][wd]
__device__ float              g_alpha[COUT];
__device__ int                g_sum[COUT];
__device__ unsigned long long g_sumsq[COUT];
__device__ float              g_scale[COUT];
__device__ float              g_shift[COUT];
__device__ short              g_S[BATCH * NPIX * COUT];         // [b][p][co] 51.4 MB

// carry-save adder: 2 LOP3 (0x96 xor3, 0xE8 maj3)
__device__ __forceinline__ void csa(unsigned a, unsigned b, unsigned c,
                                    unsigned& s, unsigned& cy) {
    s  = a ^ b ^ c;
    cy = (a & b) | (a & c) | (b & c);
}

// ----------------- kernel 1: zero the stats accumulators -----------------
__global__ void zero_stats_kernel() {
    int t = threadIdx.x;
    if (t < COUT) { g_sum[t] = 0; g_sumsq[t] = 0ull; }
}

// ----------------- kernel 2: weight prep -----------------
__global__ void __launch_bounds__(256) prep_w_kernel(const float* __restrict__ w) {
    int co   = blockIdx.x;
    int ci   = threadIdx.x;           // 0..255
    int lane = ci & 31;
    int warp = ci >> 5;               // = word index (ci/32)

    float v[9];
    const float* wp = w + ((size_t)co * CIN + ci) * 9;
#pragma unroll
    for (int t = 0; t < 9; t++) v[t] = wp[t];

    __shared__ float part[8][9];
    __shared__ float tapmean[9];

#pragma unroll
    for (int t = 0; t < 9; t++) {
        float s = v[t];
#pragma unroll
        for (int o = 16; o > 0; o >>= 1) s += __shfl_down_sync(0xffffffffu, s, o);
        if (lane == 0) part[warp][t] = s;
    }
    __syncthreads();
    if (ci < 9) {
        float s = 0.f;
#pragma unroll
        for (int i = 0; i < 8; i++) s += part[i][ci];
        tapmean[ci] = s * (1.0f / 256.0f);
    }
    __syncthreads();

    float asum = 0.f;
#pragma unroll
    for (int t = 0; t < 9; t++) {
        float wc = v[t] - tapmean[t];
        wc = fminf(fmaxf(wc, -1.0f), 1.0f);
        asum += fabsf(wc);
        unsigned m = __ballot_sync(0xffffffffu, wc < 0.0f);
        if (lane == 0) g_wbits[co * 72 + t * CW + warp] = m;
    }
    __syncthreads();
#pragma unroll
    for (int o = 16; o > 0; o >>= 1) asum += __shfl_down_sync(0xffffffffu, asum, o);
    if (lane == 0) part[warp][0] = asum;
    __syncthreads();
    if (ci == 0) {
        float tot = 0.f;
#pragma unroll
        for (int i = 0; i < 8; i++) tot += part[i][0];
        g_alpha[co] = tot * (1.0f / 2304.0f);
    }
}

// ----------------- kernel 3: binarize x into bit-planes -----------------
__global__ void __launch_bounds__(256) binarize_kernel(const float* __restrict__ x) {
    int idx = blockIdx.x * 256 + threadIdx.x;       // 0 .. BATCH*CW*NPIX-1
    if (idx >= BATCH * CW * NPIX) return;
    int p  = idx % NPIX;
    int wd = (idx / NPIX) % CW;
    int b  = idx / (NPIX * CW);

    const float* xp = x + ((size_t)(b * CIN + wd * 32) * NPIX) + p;
    unsigned m = 0u;
#pragma unroll
    for (int k = 0; k < 32; k++) {
        float v = xp[(size_t)k * NPIX];
        m |= (v < 0.0f ? 1u : 0u) << k;
    }
    g_xbits[((size_t)(b * NPIX + p)) * CW + wd] = m;
}

// ----------------- kernel 4: XNOR conv via CSA-compressed popcount -----------------
// Block = (h, b), 512 threads. Thread pair (2i, 2i+1): cout i, ci halves [0,128)/[128,256).
// P = sum popc(x^w) over 36 words computed with a Harley-Seal CSA tree: 7 POPCs.
__global__ void __launch_bounds__(512) conv_kernel() {
    int h   = blockIdx.x;      // 0..55
    int b   = blockIdx.y;      // 0..31
    int tid = threadIdx.x;     // 0..511
    int co   = tid >> 1;       // 0..255
    int half = tid & 1;        // 0 = words 0-3, 1 = words 4-7

    __shared__ unsigned sx[3][Ww + 2][CW];    // zero-padded cols 0 and 57

    for (int i = tid; i < 3 * (Ww + 2) * CW; i += 512) ((unsigned*)sx)[i] = 0u;
    __syncthreads();
#pragma unroll
    for (int r = 0; r < 3; r++) {
        int gh = h - 1 + r;
        if (gh >= 0 && gh < Hh) {
            const unsigned* src = g_xbits + ((size_t)(b * NPIX + gh * Ww)) * CW;
            unsigned* dst = &sx[r][1][0];
            for (int i = tid; i < Ww * CW; i += 512) dst[i] = src[i];
        }
    }
    __syncthreads();

    // per-thread weights: 9 taps x 4 words (this half)
    unsigned wreg[36];
    {
        const unsigned* wp = g_wbits + co * 72 + half * 4;
#pragma unroll
        for (int t = 0; t < 9; t++) {
            uint4 q = *(const uint4*)(wp + t * CW);
            wreg[t * 4 + 0] = q.x; wreg[t * 4 + 1] = q.y;
            wreg[t * 4 + 2] = q.z; wreg[t * 4 + 3] = q.w;
        }
    }
    // per-tap weight popcounts (this half) for border corrections
    int nw[9];
#pragma unroll
    for (int t = 0; t < 9; t++)
        nw[t] = __popc(wreg[t*4]) + __popc(wreg[t*4+1]) + __popc(wreg[t*4+2]) + __popc(wreg[t*4+3]);

    int rowInv = (h == 0) ? 0 : (h == Hh - 1) ? 2 : -1;
    int corrH = 0, nvH = 9;
    if (rowInv >= 0) { corrH = nw[rowInv*3+0] + nw[rowInv*3+1] + nw[rowInv*3+2]; nvH = 6; }
    int nwc0 = nw[0] + nw[3] + nw[6];
    int nwc2 = nw[2] + nw[5] + nw[8];
    int rflag = (rowInv >= 0) ? 1 : 0;

    short* sout = g_S + ((size_t)(b * NPIX) + h * Ww) * COUT + co;
    int lsum = 0, lsq = 0;

#pragma unroll 2
    for (int w = 0; w < Ww; w++) {
        // ---- level 0: 12 CSAs over XORed triples (rows 0,1,2 of each col/word) ----
        unsigned s1[12], c2[12];
#pragma unroll
        for (int c = 0; c < 3; c++) {
            uint4 x0 = *(const uint4*)(&sx[0][w + c][half * 4]);
            uint4 x1 = *(const uint4*)(&sx[1][w + c][half * 4]);
            uint4 x2 = *(const uint4*)(&sx[2][w + c][half * 4]);
            unsigned xa[4] = {x0.x, x0.y, x0.z, x0.w};
            unsigned xb[4] = {x1.x, x1.y, x1.z, x1.w};
            unsigned xc[4] = {x2.x, x2.y, x2.z, x2.w};
#pragma unroll
            for (int j = 0; j < 4; j++) {
                unsigned e0 = xa[j] ^ wreg[(0 * 3 + c) * 4 + j];
                unsigned e1 = xb[j] ^ wreg[(1 * 3 + c) * 4 + j];
                unsigned e2 = xc[j] ^ wreg[(2 * 3 + c) * 4 + j];
                csa(e0, e1, e2, s1[c * 4 + j], c2[c * 4 + j]);
            }
        }
        // ---- weight-1 compression: 12 -> 4 -> (1 + leftover) ----
        unsigned sa[4], ca[4];
        csa(s1[0], s1[1],  s1[2],  sa[0], ca[0]);
        csa(s1[3], s1[4],  s1[5],  sa[1], ca[1]);
        csa(s1[6], s1[7],  s1[8],  sa[2], ca[2]);
        csa(s1[9], s1[10], s1[11], sa[3], ca[3]);
        unsigned sb, cb;
        csa(sa[0], sa[1], sa[2], sb, cb);
        int p1 = __popc(sb) + __popc(sa[3]);                 // weight 1 (2 POPC)

        // ---- weight-2 pool: c2[12] + ca[4] + cb = 17 words ----
        unsigned s2[5], c4[5];
        csa(c2[0], c2[1],  c2[2],  s2[0], c4[0]);
        csa(c2[3], c2[4],  c2[5],  s2[1], c4[1]);
        csa(c2[6], c2[7],  c2[8],  s2[2], c4[2]);
        csa(c2[9], c2[10], c2[11], s2[3], c4[3]);
        csa(ca[0], ca[1],  ca[2],  s2[4], c4[4]);
        // remaining weight-2 words: ca[3], cb ; pool = s2[0..4] + ca[3] + cb = 7
        unsigned s2b[2], c4b[2];
        csa(s2[0], s2[1], s2[2], s2b[0], c4b[0]);
        csa(s2[3], s2[4], ca[3], s2b[1], c4b[1]);
        unsigned s2c, c4c;
        csa(s2b[0], s2b[1], cb, s2c, c4c);
        int p2 = __popc(s2c);                                 // weight 2 (1 POPC)

        // ---- weight-4 pool: c4[0..4] + c4b[0..1] + c4c = 8 words ----
        unsigned s4[2], c8[2];
        csa(c4[0], c4[1], c4[2], s4[0], c8[0]);
        csa(c4[3], c4[4], c4b[0], s4[1], c8[1]);
        unsigned s4b, c8b;
        csa(s4[0], s4[1], c4b[1], s4b, c8b);
        int p4 = __popc(s4b) + __popc(c4c);                   // weight 4 (2 POPC)

        // ---- weight-8 pool: c8[0], c8[1], c8b = 3 words ----
        unsigned s8, c16;
        csa(c8[0], c8[1], c8b, s8, c16);
        int p8  = __popc(s8);                                 // weight 8
        int p16 = __popc(c16);                                // weight 16

        int P = p1 + 2 * p2 + 4 * p4 + 8 * p8 + 16 * p16;

        int nvalid = nvH, corr = corrH;
        if (w == 0) {
            nvalid = nvH - 3 + rflag;
            corr   = corrH + nwc0 - (rflag ? nw[rowInv*3+0] : 0);
        } else if (w == Ww - 1) {
            nvalid = nvH - 3 + rflag;
            corr   = corrH + nwc2 - (rflag ? nw[rowInv*3+2] : 0);
        }
        int Sh = 128 * nvalid - 2 * P + 2 * corr;      // half contribution
        int S  = Sh + __shfl_xor_sync(0xffffffffu, Sh, 1);
        if (half == 0) {
            sout[(size_t)w * COUT] = (short)S;
            lsum += S;
            lsq  += S * S;        // <= 56*2304^2 = 2.97e8 < INT_MAX
        }
    }
    if (half == 0) {
        atomicAdd(&g_sum[co], lsum);
        atomicAdd(&g_sumsq[co], (unsigned long long)(long long)lsq);
    }
}

// ----------------- kernel 5: finalize per-channel thresholds -----------------
__global__ void finalize_kernel(const float* __restrict__ gamma,
                                const float* __restrict__ beta) {
    int co = threadIdx.x;
    if (co >= COUT) return;
    double s    = (double)g_sum[co];
    double sq   = (double)(long long)g_sumsq[co];
    double mean = s / NVALS;
    double var  = sq / NVALS - mean * mean;            // exact var of integer S
    double a    = (double)g_alpha[co];
    double inv  = 1.0 / sqrt(a * a * var + BN_EPS);
    double sc   = (double)gamma[co] * a * inv;
    g_scale[co] = (float)sc;
    g_shift[co] = (float)((double)beta[co] - sc * mean);
}

// ----------------- kernel 6: threshold + transpose [b][p][co] -> [b][co][p] -----------------
__global__ void __launch_bounds__(256) thresh_kernel(float* __restrict__ out) {
    __shared__ float tile[32][33];
    int p0  = blockIdx.x * 32;     // 98 tiles (3136 = 98*32)
    int co0 = blockIdx.y * 32;     // 8 tiles
    int b   = blockIdx.z;
    int tx  = threadIdx.x;         // 0..31
    int ty  = threadIdx.y;         // 0..7

    float sc = g_scale[co0 + tx];
    float sh = g_shift[co0 + tx];
#pragma unroll
    for (int r = 0; r < 4; r++) {
        int pl = ty * 4 + r;
        short s = g_S[((size_t)(b * NPIX + p0 + pl)) * COUT + co0 + tx];
        tile[pl][tx] = (fmaf(sc, (float)s, sh) > 0.0f) ? 1.0f : 0.0f;
    }
    __syncthreads();
#pragma unroll
    for (int r = 0; r < 4; r++) {
        int cl = ty * 4 + r;
        out[((size_t)(b * COUT + co0 + cl)) * NPIX + p0 + tx] = tile[tx][cl];
    }
}

// ----------------- launch -----------------
extern "C" void kernel_launch(void* const* d_in, const int* in_sizes, int n_in,
                              void* d_out, int out_size) {
    const float* x      = (const float*)d_in[0];
    const float* weight = (const float*)d_in[1];
    // const float* bias = (const float*)d_in[2];  // cancels inside BN; unused
    const float* gamma  = (const float*)d_in[3];
    const float* beta   = (const float*)d_in[4];
    float* out = (float*)d_out;

    zero_stats_kernel<<<1, 256>>>();
    prep_w_kernel<<<COUT, 256>>>(weight);
    {
        int nwords = BATCH * CW * NPIX;
        binarize_kernel<<<(nwords + 255) / 256, 256>>>(x);
    }
    conv_kernel<<<dim3(Hh, BATCH), 512>>>();
    finalize_kernel<<<1, 256>>>(gamma, beta);
    thresh_kernel<<<dim3(NPIX / 32, COUT / 32, BATCH), dim3(32, 8)>>>(out);
}

// round 11
// speedup vs baseline: 4.1281x; 1.0961x over previous
#include <cuda_runtime.h>
#include <cuda_bf16.h>
#include <cstdint>

// Problem constants
#define BATCH 32
#define CIN   256
#define COUT  256
#define Hh    56
#define Ww    56
#define NPIX  (Hh*Ww)          // 3136
#define CW    8                // 256 bits = 8 x uint32 words per pixel
#define NVALS 100352.0         // BATCH*NPIX per-channel count
#define BN_EPS 1e-5

// ----------------- scratch (device globals; no allocation) -----------------
__device__ unsigned           g_xbits[BATCH * NPIX * CW];       // [b][p][wd]  3.2 MB
__device__ unsigned           g_wbits[COUT * 9 * CW];           // [co][tap][wd]
__device__ float              g_alpha[COUT];
__device__ int                g_sum[COUT];
__device__ unsigned long long g_sumsq[COUT];
__device__ float              g_scale[COUT];
__device__ float              g_shift[COUT];
__device__ short              g_S[BATCH * NPIX * COUT];         // [b][p][co] 51.4 MB

// carry-save adder: 2 LOP3 (0x96 xor3, 0xE8 maj3)
__device__ __forceinline__ void csa(unsigned a, unsigned b, unsigned c,
                                    unsigned& s, unsigned& cy) {
    s  = a ^ b ^ c;
    cy = (a & b) | (a & c) | (b & c);
}

// ----------------- kernel 1: zero the stats accumulators -----------------
__global__ void zero_stats_kernel() {
    int t = threadIdx.x;
    if (t < COUT) { g_sum[t] = 0; g_sumsq[t] = 0ull; }
}

// ----------------- kernel 2: weight prep -----------------
__global__ void __launch_bounds__(256) prep_w_kernel(const float* __restrict__ w) {
    int co   = blockIdx.x;
    int ci   = threadIdx.x;           // 0..255
    int lane = ci & 31;
    int warp = ci >> 5;               // = word index (ci/32)

    float v[9];
    const float* wp = w + ((size_t)co * CIN + ci) * 9;
#pragma unroll
    for (int t = 0; t < 9; t++) v[t] = wp[t];

    __shared__ float part[8][9];
    __shared__ float tapmean[9];

#pragma unroll
    for (int t = 0; t < 9; t++) {
        float s = v[t];
#pragma unroll
        for (int o = 16; o > 0; o >>= 1) s += __shfl_down_sync(0xffffffffu, s, o);
        if (lane == 0) part[warp][t] = s;
    }
    __syncthreads();
    if (ci < 9) {
        float s = 0.f;
#pragma unroll
        for (int i = 0; i < 8; i++) s += part[i][ci];
        tapmean[ci] = s * (1.0f / 256.0f);
    }
    __syncthreads();

    float asum = 0.f;
#pragma unroll
    for (int t = 0; t < 9; t++) {
        float wc = v[t] - tapmean[t];
        wc = fminf(fmaxf(wc, -1.0f), 1.0f);
        asum += fabsf(wc);
        unsigned m = __ballot_sync(0xffffffffu, wc < 0.0f);
        if (lane == 0) g_wbits[co * 72 + t * CW + warp] = m;
    }
    __syncthreads();
#pragma unroll
    for (int o = 16; o > 0; o >>= 1) asum += __shfl_down_sync(0xffffffffu, asum, o);
    if (lane == 0) part[warp][0] = asum;
    __syncthreads();
    if (ci == 0) {
        float tot = 0.f;
#pragma unroll
        for (int i = 0; i < 8; i++) tot += part[i][0];
        g_alpha[co] = tot * (1.0f / 2304.0f);
    }
}

// ----------------- kernel 3: binarize x into bit-planes -----------------
__global__ void __launch_bounds__(256) binarize_kernel(const float* __restrict__ x) {
    int idx = blockIdx.x * 256 + threadIdx.x;       // 0 .. BATCH*CW*NPIX-1
    if (idx >= BATCH * CW * NPIX) return;
    int p  = idx % NPIX;
    int wd = (idx / NPIX) % CW;
    int b  = idx / (NPIX * CW);

    const float* xp = x + ((size_t)(b * CIN + wd * 32) * NPIX) + p;
    unsigned m = 0u;
#pragma unroll
    for (int k = 0; k < 32; k++) {
        float v = xp[(size_t)k * NPIX];
        m |= (v < 0.0f ? 1u : 0u) << k;
    }
    g_xbits[((size_t)(b * NPIX + p)) * CW + wd] = m;
}

// ----------------- kernel 4: XNOR conv, pipe-balanced CSA/POPC -----------------
// Block = (h, b), 512 threads. Thread pair (2i, 2i+1): cout i, ci halves [0,128)/[128,256).
// Level-0 CSA (alu pipe) + shallow w1 compression, then POPC 20 words (popc pipe):
//   P = p1 + 2*p2   (exact: popc(a)+popc(b)+popc(c) = popc(s) + 2*popc(maj))
__global__ void __launch_bounds__(512) conv_kernel() {
    int h   = blockIdx.x;      // 0..55
    int b   = blockIdx.y;      // 0..31
    int tid = threadIdx.x;     // 0..511
    int co   = tid >> 1;       // 0..255
    int half = tid & 1;        // 0 = words 0-3, 1 = words 4-7

    __shared__ unsigned sx[3][Ww + 2][CW];    // zero-padded cols 0 and 57

    for (int i = tid; i < 3 * (Ww + 2) * CW; i += 512) ((unsigned*)sx)[i] = 0u;
    __syncthreads();
#pragma unroll
    for (int r = 0; r < 3; r++) {
        int gh = h - 1 + r;
        if (gh >= 0 && gh < Hh) {
            const unsigned* src = g_xbits + ((size_t)(b * NPIX + gh * Ww)) * CW;
            unsigned* dst = &sx[r][1][0];
            for (int i = tid; i < Ww * CW; i += 512) dst[i] = src[i];
        }
    }
    __syncthreads();

    // per-thread weights: 9 taps x 4 words (this half)
    unsigned wreg[36];
    {
        const unsigned* wp = g_wbits + co * 72 + half * 4;
#pragma unroll
        for (int t = 0; t < 9; t++) {
            uint4 q = *(const uint4*)(wp + t * CW);
            wreg[t * 4 + 0] = q.x; wreg[t * 4 + 1] = q.y;
            wreg[t * 4 + 2] = q.z; wreg[t * 4 + 3] = q.w;
        }
    }
    // per-tap weight popcounts (this half) for border corrections
    int nw[9];
#pragma unroll
    for (int t = 0; t < 9; t++)
        nw[t] = __popc(wreg[t*4]) + __popc(wreg[t*4+1]) + __popc(wreg[t*4+2]) + __popc(wreg[t*4+3]);

    int rowInv = (h == 0) ? 0 : (h == Hh - 1) ? 2 : -1;
    int corrH = 0, nvH = 9;
    if (rowInv >= 0) { corrH = nw[rowInv*3+0] + nw[rowInv*3+1] + nw[rowInv*3+2]; nvH = 6; }
    int nwc0 = nw[0] + nw[3] + nw[6];
    int nwc2 = nw[2] + nw[5] + nw[8];
    int rflag = (rowInv >= 0) ? 1 : 0;

    short* sout = g_S + ((size_t)(b * NPIX) + h * Ww) * COUT + co;
    int lsum = 0, lsq = 0;

    // compute P for window position w (this half)
    auto computeP = [&](int w) -> int {
        unsigned s1[12], c2[12];
#pragma unroll
        for (int c = 0; c < 3; c++) {
            uint4 x0 = *(const uint4*)(&sx[0][w + c][half * 4]);
            uint4 x1 = *(const uint4*)(&sx[1][w + c][half * 4]);
            uint4 x2 = *(const uint4*)(&sx[2][w + c][half * 4]);
            unsigned xa[4] = {x0.x, x0.y, x0.z, x0.w};
            unsigned xb[4] = {x1.x, x1.y, x1.z, x1.w};
            unsigned xc[4] = {x2.x, x2.y, x2.z, x2.w};
#pragma unroll
            for (int j = 0; j < 4; j++) {
                unsigned e0 = xa[j] ^ wreg[(0 * 3 + c) * 4 + j];
                unsigned e1 = xb[j] ^ wreg[(1 * 3 + c) * 4 + j];
                unsigned e2 = xc[j] ^ wreg[(2 * 3 + c) * 4 + j];
                csa(e0, e1, e2, s1[c * 4 + j], c2[c * 4 + j]);
            }
        }
        // shallow weight-1 compression: 12 -> 4 (+4 carries into w2 pool)
        unsigned sa[4], ca[4];
        csa(s1[0], s1[1],  s1[2],  sa[0], ca[0]);
        csa(s1[3], s1[4],  s1[5],  sa[1], ca[1]);
        csa(s1[6], s1[7],  s1[8],  sa[2], ca[2]);
        csa(s1[9], s1[10], s1[11], sa[3], ca[3]);

        // POPC pipe does the rest: 4 w1-words + 16 w2-words
        int p1 = __popc(sa[0]) + __popc(sa[1]) + __popc(sa[2]) + __popc(sa[3]);
        int p2 = __popc(c2[0]) + __popc(c2[1]) + __popc(c2[2]) + __popc(c2[3])
               + __popc(c2[4]) + __popc(c2[5]) + __popc(c2[6]) + __popc(c2[7])
               + __popc(c2[8]) + __popc(c2[9]) + __popc(c2[10]) + __popc(c2[11])
               + __popc(ca[0]) + __popc(ca[1]) + __popc(ca[2]) + __popc(ca[3]);
        return p1 + 2 * p2;
    };

    auto emit = [&](int w, int nvalid, int corr) {
        int P  = computeP(w);
        int Sh = 128 * nvalid - 2 * P + 2 * corr;      // half contribution
        int S  = Sh + __shfl_xor_sync(0xffffffffu, Sh, 1);
        if (half == 0) {
            sout[(size_t)w * COUT] = (short)S;
            lsum += S;
            lsq  += S * S;        // <= 56*2304^2 = 2.97e8 < INT_MAX
        }
    };

    // peel borders: interior loop has no border selects
    emit(0, nvH - 3 + rflag, corrH + nwc0 - (rflag ? nw[rowInv*3+0] : 0));
#pragma unroll 2
    for (int w = 1; w < Ww - 1; w++) emit(w, nvH, corrH);
    emit(Ww - 1, nvH - 3 + rflag, corrH + nwc2 - (rflag ? nw[rowInv*3+2] : 0));

    if (half == 0) {
        atomicAdd(&g_sum[co], lsum);
        atomicAdd(&g_sumsq[co], (unsigned long long)(long long)lsq);
    }
}

// ----------------- kernel 5: finalize per-channel thresholds -----------------
__global__ void finalize_kernel(const float* __restrict__ gamma,
                                const float* __restrict__ beta) {
    int co = threadIdx.x;
    if (co >= COUT) return;
    double s    = (double)g_sum[co];
    double sq   = (double)(long long)g_sumsq[co];
    double mean = s / NVALS;
    double var  = sq / NVALS - mean * mean;            // exact var of integer S
    double a    = (double)g_alpha[co];
    double inv  = 1.0 / sqrt(a * a * var + BN_EPS);
    double sc   = (double)gamma[co] * a * inv;
    g_scale[co] = (float)sc;
    g_shift[co] = (float)((double)beta[co] - sc * mean);
}

// ----------------- kernel 6: threshold + transpose [b][p][co] -> [b][co][p] -----------------
__global__ void __launch_bounds__(256) thresh_kernel(float* __restrict__ out) {
    __shared__ float tile[32][33];
    int p0  = blockIdx.x * 32;     // 98 tiles (3136 = 98*32)
    int co0 = blockIdx.y * 32;     // 8 tiles
    int b   = blockIdx.z;
    int tx  = threadIdx.x;         // 0..31
    int ty  = threadIdx.y;         // 0..7

    float sc = g_scale[co0 + tx];
    float sh = g_shift[co0 + tx];
#pragma unroll
    for (int r = 0; r < 4; r++) {
        int pl = ty * 4 + r;
        short s = g_S[((size_t)(b * NPIX + p0 + pl)) * COUT + co0 + tx];
        tile[pl][tx] = (fmaf(sc, (float)s, sh) > 0.0f) ? 1.0f : 0.0f;
    }
    __syncthreads();
#pragma unroll
    for (int r = 0; r < 4; r++) {
        int cl = ty * 4 + r;
        out[((size_t)(b * COUT + co0 + cl)) * NPIX + p0 + tx] = tile[tx][cl];
    }
}

// ----------------- launch -----------------
extern "C" void kernel_launch(void* const* d_in, const int* in_sizes, int n_in,
                              void* d_out, int out_size) {
    const float* x      = (const float*)d_in[0];
    const float* weight = (const float*)d_in[1];
    // const float* bias = (const float*)d_in[2];  // cancels inside BN; unused
    const float* gamma  = (const float*)d_in[3];
    const float* beta   = (const float*)d_in[4];
    float* out = (float*)d_out;

    zero_stats_kernel<<<1, 256>>>();
    prep_w_kernel<<<COUT, 256>>>(weight);
    {
        int nwords = BATCH * CW * NPIX;
        binarize_kernel<<<(nwords + 255) / 256, 256>>>(x);
    }
    conv_kernel<<<dim3(Hh, BATCH), 512>>>();
    finalize_kernel<<<1, 256>>>(gamma, beta);
    thresh_kernel<<<dim3(NPIX / 32, COUT / 32, BATCH), dim3(32, 8)>>>(out);
}

// round 13
// speedup vs baseline: 4.2849x; 1.0380x over previous
#include <cuda_runtime.h>
#include <cuda_bf16.h>
#include <cstdint>

// Problem constants
#define BATCH 32
#define CIN   256
#define COUT  256
#define Hh    56
#define Ww    56
#define NPIX  (Hh*Ww)          // 3136
#define CW    8                // 256 bits = 8 x uint32 words per pixel
#define NVALS 100352.0         // BATCH*NPIX per-channel count
#define BN_EPS 1e-5

// ----------------- scratch (device globals; no allocation) -----------------
__device__ unsigned           g_xbits[BATCH * NPIX * CW];       // [b][p][wd]  3.2 MB
__device__ unsigned           g_wbits[COUT * 9 * CW];           // [co][tap][wd]
__device__ float              g_alpha[COUT];
__device__ int                g_sum[COUT];
__device__ unsigned long long g_sumsq[COUT];
__device__ float              g_scale[COUT];
__device__ float              g_shift[COUT];
__device__ short              g_S[BATCH * NPIX * COUT];         // [b][p][co] 51.4 MB

// carry-save adder: 2 LOP3 (0x96 xor3, 0xE8 maj3)
__device__ __forceinline__ void csa(unsigned a, unsigned b, unsigned c,
                                    unsigned& s, unsigned& cy) {
    s  = a ^ b ^ c;
    cy = (a & b) | (a & c) | (b & c);
}

// ----------------- kernel 1: zero the stats accumulators -----------------
__global__ void zero_stats_kernel() {
    int t = threadIdx.x;
    if (t < COUT) { g_sum[t] = 0; g_sumsq[t] = 0ull; }
}

// ----------------- kernel 2: weight prep -----------------
__global__ void __launch_bounds__(256) prep_w_kernel(const float* __restrict__ w) {
    int co   = blockIdx.x;
    int ci   = threadIdx.x;           // 0..255
    int lane = ci & 31;
    int warp = ci >> 5;               // = word index (ci/32)

    float v[9];
    const float* wp = w + ((size_t)co * CIN + ci) * 9;
#pragma unroll
    for (int t = 0; t < 9; t++) v[t] = wp[t];

    __shared__ float part[8][9];
    __shared__ float tapmean[9];

#pragma unroll
    for (int t = 0; t < 9; t++) {
        float s = v[t];
#pragma unroll
        for (int o = 16; o > 0; o >>= 1) s += __shfl_down_sync(0xffffffffu, s, o);
        if (lane == 0) part[warp][t] = s;
    }
    __syncthreads();
    if (ci < 9) {
        float s = 0.f;
#pragma unroll
        for (int i = 0; i < 8; i++) s += part[i][ci];
        tapmean[ci] = s * (1.0f / 256.0f);
    }
    __syncthreads();

    float asum = 0.f;
#pragma unroll
    for (int t = 0; t < 9; t++) {
        float wc = v[t] - tapmean[t];
        wc = fminf(fmaxf(wc, -1.0f), 1.0f);
        asum += fabsf(wc);
        unsigned m = __ballot_sync(0xffffffffu, wc < 0.0f);
        if (lane == 0) g_wbits[co * 72 + t * CW + warp] = m;
    }
    __syncthreads();
#pragma unroll
    for (int o = 16; o > 0; o >>= 1) asum += __shfl_down_sync(0xffffffffu, asum, o);
    if (lane == 0) part[warp][0] = asum;
    __syncthreads();
    if (ci == 0) {
        float tot = 0.f;
#pragma unroll
        for (int i = 0; i < 8; i++) tot += part[i][0];
        g_alpha[co] = tot * (1.0f / 2304.0f);
    }
}

// ----------------- kernel 3: binarize x into bit-planes -----------------
__global__ void __launch_bounds__(256) binarize_kernel(const float* __restrict__ x) {
    int idx = blockIdx.x * 256 + threadIdx.x;       // 0 .. BATCH*CW*NPIX-1
    if (idx >= BATCH * CW * NPIX) return;
    int p  = idx % NPIX;
    int wd = (idx / NPIX) % CW;
    int b  = idx / (NPIX * CW);

    const float* xp = x + ((size_t)(b * CIN + wd * 32) * NPIX) + p;
    unsigned m = 0u;
#pragma unroll
    for (int k = 0; k < 32; k++) {
        float v = xp[(size_t)k * NPIX];
        m |= (v < 0.0f ? 1u : 0u) << k;
    }
    g_xbits[((size_t)(b * NPIX + p)) * CW + wd] = m;
}

// ----------------- kernel 4: XNOR conv, dual-row blocks, CSA/POPC balanced -----------------
// Block = (hb, b): h-rows 2*hb and 2*hb+1. 512 threads; pair (2i,2i+1) = cout i,
// ci halves [0,128)/[128,256). Two interleaved CSA trees (one per row) share
// x-row loads and double ILP. P = p1 + 2*p2 per tree (exact integer identity).
// Border column identity (from R11, verified): nvalid = nv - 3 + rflag,
// corr += nwc - (rflag ? corner : 0).
__global__ void __launch_bounds__(512) conv_kernel() {
    int hb  = blockIdx.x;      // 0..27
    int b   = blockIdx.y;      // 0..31
    int h0  = hb * 2;          // row A
    int h1  = h0 + 1;          // row B
    int tid = threadIdx.x;     // 0..511
    int co   = tid >> 1;       // 0..255
    int half = tid & 1;        // 0 = words 0-3, 1 = words 4-7

    __shared__ unsigned sx[4][Ww + 2][CW];    // tile rows h0-1 .. h0+2, padded cols

    for (int i = tid; i < 4 * (Ww + 2) * CW; i += 512) ((unsigned*)sx)[i] = 0u;
    __syncthreads();
#pragma unroll
    for (int r = 0; r < 4; r++) {
        int gh = h0 - 1 + r;
        if (gh >= 0 && gh < Hh) {
            const unsigned* src = g_xbits + ((size_t)(b * NPIX + gh * Ww)) * CW;
            unsigned* dst = &sx[r][1][0];
            for (int i = tid; i < Ww * CW; i += 512) dst[i] = src[i];
        }
    }
    __syncthreads();

    // per-thread weights: 9 taps x 4 words (this half)
    unsigned wreg[36];
    {
        const unsigned* wp = g_wbits + co * 72 + half * 4;
#pragma unroll
        for (int t = 0; t < 9; t++) {
            uint4 q = *(const uint4*)(wp + t * CW);
            wreg[t * 4 + 0] = q.x; wreg[t * 4 + 1] = q.y;
            wreg[t * 4 + 2] = q.z; wreg[t * 4 + 3] = q.w;
        }
    }
    // per-tap weight popcounts (this half) for border corrections
    int nw[9];
#pragma unroll
    for (int t = 0; t < 9; t++)
        nw[t] = __popc(wreg[t*4]) + __popc(wreg[t*4+1]) + __popc(wreg[t*4+2]) + __popc(wreg[t*4+3]);

    int nwc0 = nw[0] + nw[3] + nw[6];
    int nwc2 = nw[2] + nw[5] + nw[8];

    // row A (h0): only possible invalid row is tap-row 0 (h0==0)
    int rflagA = (h0 == 0) ? 1 : 0;
    int nvA    = rflagA ? 6 : 9;
    int corrA  = rflagA ? (nw[0] + nw[1] + nw[2]) : 0;
    int cornA  = rflagA ? nw[0] : 0;     // corner tap for w=0
    int cornA2 = rflagA ? nw[2] : 0;     // corner tap for w=55
    // row B (h1): only possible invalid row is tap-row 2 (h1==55)
    int rflagB = (h1 == Hh - 1) ? 1 : 0;
    int nvB    = rflagB ? 6 : 9;
    int corrB  = rflagB ? (nw[6] + nw[7] + nw[8]) : 0;
    int cornB  = rflagB ? nw[6] : 0;     // corner tap for w=0
    int cornB2 = rflagB ? nw[8] : 0;     // corner tap for w=55

    short* soutA = g_S + ((size_t)(b * NPIX) + h0 * Ww) * COUT + co;
    short* soutB = g_S + ((size_t)(b * NPIX) + h1 * Ww) * COUT + co;
    int lsum = 0, lsq = 0;

    // compute P for both rows at window position w
    auto computeP2 = [&](int w, int& PA, int& PB) {
        unsigned s1A[12], c2A[12], s1B[12], c2B[12];
#pragma unroll
        for (int c = 0; c < 3; c++) {
            uint4 x0 = *(const uint4*)(&sx[0][w + c][half * 4]);
            uint4 x1 = *(const uint4*)(&sx[1][w + c][half * 4]);
            uint4 x2 = *(const uint4*)(&sx[2][w + c][half * 4]);
            uint4 x3 = *(const uint4*)(&sx[3][w + c][half * 4]);
            unsigned r0[4] = {x0.x, x0.y, x0.z, x0.w};
            unsigned r1[4] = {x1.x, x1.y, x1.z, x1.w};
            unsigned r2[4] = {x2.x, x2.y, x2.z, x2.w};
            unsigned r3[4] = {x3.x, x3.y, x3.z, x3.w};
#pragma unroll
            for (int j = 0; j < 4; j++) {
                unsigned w0 = wreg[(0 * 3 + c) * 4 + j];
                unsigned w1 = wreg[(1 * 3 + c) * 4 + j];
                unsigned w2 = wreg[(2 * 3 + c) * 4 + j];
                csa(r0[j] ^ w0, r1[j] ^ w1, r2[j] ^ w2, s1A[c * 4 + j], c2A[c * 4 + j]);
                csa(r1[j] ^ w0, r2[j] ^ w1, r3[j] ^ w2, s1B[c * 4 + j], c2B[c * 4 + j]);
            }
        }
        // shallow weight-1 compression (12 -> 4) + POPC, per tree
        unsigned sa0, sa1, sa2, sa3, ca0, ca1, ca2, ca3;
        csa(s1A[0], s1A[1],  s1A[2],  sa0, ca0);
        csa(s1A[3], s1A[4],  s1A[5],  sa1, ca1);
        csa(s1A[6], s1A[7],  s1A[8],  sa2, ca2);
        csa(s1A[9], s1A[10], s1A[11], sa3, ca3);
        int p1A = __popc(sa0) + __popc(sa1) + __popc(sa2) + __popc(sa3);
        int p2A = __popc(c2A[0]) + __popc(c2A[1]) + __popc(c2A[2]) + __popc(c2A[3])
                + __popc(c2A[4]) + __popc(c2A[5]) + __popc(c2A[6]) + __popc(c2A[7])
                + __popc(c2A[8]) + __popc(c2A[9]) + __popc(c2A[10]) + __popc(c2A[11])
                + __popc(ca0) + __popc(ca1) + __popc(ca2) + __popc(ca3);
        PA = p1A + 2 * p2A;

        unsigned sb0, sb1, sb2, sb3, cb0, cb1, cb2, cb3;
        csa(s1B[0], s1B[1],  s1B[2],  sb0, cb0);
        csa(s1B[3], s1B[4],  s1B[5],  sb1, cb1);
        csa(s1B[6], s1B[7],  s1B[8],  sb2, cb2);
        csa(s1B[9], s1B[10], s1B[11], sb3, cb3);
        int p1B = __popc(sb0) + __popc(sb1) + __popc(sb2) + __popc(sb3);
        int p2B = __popc(c2B[0]) + __popc(c2B[1]) + __popc(c2B[2]) + __popc(c2B[3])
                + __popc(c2B[4]) + __popc(c2B[5]) + __popc(c2B[6]) + __popc(c2B[7])
                + __popc(c2B[8]) + __popc(c2B[9]) + __popc(c2B[10]) + __popc(c2B[11])
                + __popc(cb0) + __popc(cb1) + __popc(cb2) + __popc(cb3);
        PB = p1B + 2 * p2B;
    };

    auto emit = [&](int w, int nvalA, int corA, int nvalB, int corB) {
        int PA, PB;
        computeP2(w, PA, PB);
        int ShA = 128 * nvalA - 2 * PA + 2 * corA;
        int ShB = 128 * nvalB - 2 * PB + 2 * corB;
        int SA = ShA + __shfl_xor_sync(0xffffffffu, ShA, 1);
        int SB = ShB + __shfl_xor_sync(0xffffffffu, ShB, 1);
        if (half == 0) {
            soutA[(size_t)w * COUT] = (short)SA;
            soutB[(size_t)w * COUT] = (short)SB;
            lsum += SA + SB;
            lsq  += SA * SA + SB * SB;   // <= 112*2304^2 = 5.9e8 < INT_MAX
        }
    };

    // peel borders; border column: nvalid = nv - 3 + rflag (corner overlap)
    emit(0,      nvA - 3 + rflagA, corrA + nwc0 - cornA,
                 nvB - 3 + rflagB, corrB + nwc0 - cornB);
    for (int w = 1; w < Ww - 1; w++) emit(w, nvA, corrA, nvB, corrB);
    emit(Ww - 1, nvA - 3 + rflagA, corrA + nwc2 - cornA2,
                 nvB - 3 + rflagB, corrB + nwc2 - cornB2);

    if (half == 0) {
        atomicAdd(&g_sum[co], lsum);
        atomicAdd(&g_sumsq[co], (unsigned long long)(long long)lsq);
    }
}

// ----------------- kernel 5: finalize per-channel thresholds -----------------
__global__ void finalize_kernel(const float* __restrict__ gamma,
                                const float* __restrict__ beta) {
    int co = threadIdx.x;
    if (co >= COUT) return;
    double s    = (double)g_sum[co];
    double sq   = (double)(long long)g_sumsq[co];
    double mean = s / NVALS;
    double var  = sq / NVALS - mean * mean;            // exact var of integer S
    double a    = (double)g_alpha[co];
    double inv  = 1.0 / sqrt(a * a * var + BN_EPS);
    double sc   = (double)gamma[co] * a * inv;
    g_scale[co] = (float)sc;
    g_shift[co] = (float)((double)beta[co] - sc * mean);
}

// ----------------- kernel 6: threshold + transpose [b][p][co] -> [b][co][p] -----------------
__global__ void __launch_bounds__(256) thresh_kernel(float* __restrict__ out) {
    __shared__ float tile[32][33];
    int p0  = blockIdx.x * 32;     // 98 tiles (3136 = 98*32)
    int co0 = blockIdx.y * 32;     // 8 tiles
    int b   = blockIdx.z;
    int tx  = threadIdx.x;         // 0..31
    int ty  = threadIdx.y;         // 0..7

    float sc = g_scale[co0 + tx];
    float sh = g_shift[co0 + tx];
#pragma unroll
    for (int r = 0; r < 4; r++) {
        int pl = ty * 4 + r;
        short s = g_S[((size_t)(b * NPIX + p0 + pl)) * COUT + co0 + tx];
        tile[pl][tx] = (fmaf(sc, (float)s, sh) > 0.0f) ? 1.0f : 0.0f;
    }
    __syncthreads();
#pragma unroll
    for (int r = 0; r < 4; r++) {
        int cl = ty * 4 + r;
        out[((size_t)(b * COUT + co0 + cl)) * NPIX + p0 + tx] = tile[tx][cl];
    }
}

// ----------------- launch -----------------
extern "C" void kernel_launch(void* const* d_in, const int* in_sizes, int n_in,
                              void* d_out, int out_size) {
    const float* x      = (const float*)d_in[0];
    const float* weight = (const float*)d_in[1];
    // const float* bias = (const float*)d_in[2];  // cancels inside BN; unused
    const float* gamma  = (const float*)d_in[3];
    const float* beta   = (const float*)d_in[4];
    float* out = (float*)d_out;

    zero_stats_kernel<<<1, 256>>>();
    prep_w_kernel<<<COUT, 256>>>(weight);
    {
        int nwords = BATCH * CW * NPIX;
        binarize_kernel<<<(nwords + 255) / 256, 256>>>(x);
    }
    conv_kernel<<<dim3(Hh / 2, BATCH), 512>>>();
    finalize_kernel<<<1, 256>>>(gamma, beta);
    thresh_kernel<<<dim3(NPIX / 32, COUT / 32, BATCH), dim3(32, 8)>>>(out);
}

// round 15
// speedup vs baseline: 4.3282x; 1.0101x over previous
#include <cuda_runtime.h>
#include <cuda_bf16.h>
#include <cstdint>

// Problem constants
#define BATCH 32
#define CIN   256
#define COUT  256
#define Hh    56
#define Ww    56
#define NPIX  (Hh*Ww)          // 3136
#define CW    8                // 256 bits = 8 x uint32 words per pixel
#define NVALS 100352.0         // BATCH*NPIX per-channel count
#define BN_EPS 1e-5

// ----------------- scratch (device globals; no allocation) -----------------
__device__ unsigned           g_xbits[BATCH * NPIX * CW];       // [b][p][wd]  3.2 MB
__device__ unsigned           g_wbits[COUT * 9 * CW];           // [co][tap][wd]
__device__ float              g_alpha[COUT];
__device__ int                g_sum[COUT];
__device__ unsigned long long g_sumsq[COUT];
__device__ float              g_scale[COUT];
__device__ float              g_shift[COUT];
__device__ short              g_S[BATCH * NPIX * COUT];         // [b][p][co] 51.4 MB

// carry-save adder: 2 LOP3 (0x96 xor3, 0xE8 maj3)
__device__ __forceinline__ void csa(unsigned a, unsigned b, unsigned c,
                                    unsigned& s, unsigned& cy) {
    s  = a ^ b ^ c;
    cy = (a & b) | (a & c) | (b & c);
}

// ----------------- kernel 1: zero the stats accumulators -----------------
__global__ void zero_stats_kernel() {
    int t = threadIdx.x;
    if (t < COUT) { g_sum[t] = 0; g_sumsq[t] = 0ull; }
}

// ----------------- kernel 2: weight prep -----------------
__global__ void __launch_bounds__(256) prep_w_kernel(const float* __restrict__ w) {
    int co   = blockIdx.x;
    int ci   = threadIdx.x;           // 0..255
    int lane = ci & 31;
    int warp = ci >> 5;               // = word index (ci/32)

    float v[9];
    const float* wp = w + ((size_t)co * CIN + ci) * 9;
#pragma unroll
    for (int t = 0; t < 9; t++) v[t] = wp[t];

    __shared__ float part[8][9];
    __shared__ float tapmean[9];

#pragma unroll
    for (int t = 0; t < 9; t++) {
        float s = v[t];
#pragma unroll
        for (int o = 16; o > 0; o >>= 1) s += __shfl_down_sync(0xffffffffu, s, o);
        if (lane == 0) part[warp][t] = s;
    }
    __syncthreads();
    if (ci < 9) {
        float s = 0.f;
#pragma unroll
        for (int i = 0; i < 8; i++) s += part[i][ci];
        tapmean[ci] = s * (1.0f / 256.0f);
    }
    __syncthreads();

    float asum = 0.f;
#pragma unroll
    for (int t = 0; t < 9; t++) {
        float wc = v[t] - tapmean[t];
        wc = fminf(fmaxf(wc, -1.0f), 1.0f);
        asum += fabsf(wc);
        unsigned m = __ballot_sync(0xffffffffu, wc < 0.0f);
        if (lane == 0) g_wbits[co * 72 + t * CW + warp] = m;
    }
    __syncthreads();
#pragma unroll
    for (int o = 16; o > 0; o >>= 1) asum += __shfl_down_sync(0xffffffffu, asum, o);
    if (lane == 0) part[warp][0] = asum;
    __syncthreads();
    if (ci == 0) {
        float tot = 0.f;
#pragma unroll
        for (int i = 0; i < 8; i++) tot += part[i][0];
        g_alpha[co] = tot * (1.0f / 2304.0f);
    }
}

// ----------------- kernel 3: binarize x into bit-planes (float4, 4 pixels/thread) -----------------
__global__ void __launch_bounds__(256) binarize_kernel(const float* __restrict__ x) {
    int idx = blockIdx.x * 256 + threadIdx.x;       // 0 .. BATCH*CW*(NPIX/4)-1
    if (idx >= BATCH * CW * (NPIX / 4)) return;
    int p4 = idx % (NPIX / 4);
    int wd = (idx / (NPIX / 4)) % CW;
    int b  = idx / ((NPIX / 4) * CW);

    const float* xp = x + ((size_t)(b * CIN + wd * 32) * NPIX) + p4 * 4;
    unsigned m0 = 0u, m1 = 0u, m2 = 0u, m3 = 0u;
#pragma unroll
    for (int k = 0; k < 32; k++) {
        float4 v = *(const float4*)(xp + (size_t)k * NPIX);
        m0 |= (v.x < 0.0f ? 1u : 0u) << k;
        m1 |= (v.y < 0.0f ? 1u : 0u) << k;
        m2 |= (v.z < 0.0f ? 1u : 0u) << k;
        m3 |= (v.w < 0.0f ? 1u : 0u) << k;
    }
    size_t base = ((size_t)(b * NPIX + p4 * 4)) * CW + wd;
    g_xbits[base]          = m0;
    g_xbits[base + CW]     = m1;
    g_xbits[base + 2 * CW] = m2;
    g_xbits[base + 3 * CW] = m3;
}

// ----------------- kernel 4: XNOR conv, dual-row blocks, L0-CSA + POPC -----------------
// Block = (hb, b): h-rows 2*hb and 2*hb+1. 512 threads; pair (2i,2i+1) = cout i,
// ci halves [0,128)/[128,256). Two interleaved CSA trees (one per row) share
// x-row loads. L0 CSA only; popc the s1/c2 pools directly: P = p1 + 2*p2
// (exact: popc(a)+popc(b)+popc(c) = popc(xor3) + 2*popc(maj3)).
__global__ void __launch_bounds__(512) conv_kernel() {
    int hb  = blockIdx.x;      // 0..27
    int b   = blockIdx.y;      // 0..31
    int h0  = hb * 2;          // row A
    int h1  = h0 + 1;          // row B
    int tid = threadIdx.x;     // 0..511
    int co   = tid >> 1;       // 0..255
    int half = tid & 1;        // 0 = words 0-3, 1 = words 4-7

    __shared__ unsigned sx[4][Ww + 2][CW];    // tile rows h0-1 .. h0+2, padded cols

    for (int i = tid; i < 4 * (Ww + 2) * CW; i += 512) ((unsigned*)sx)[i] = 0u;
    __syncthreads();
#pragma unroll
    for (int r = 0; r < 4; r++) {
        int gh = h0 - 1 + r;
        if (gh >= 0 && gh < Hh) {
            const unsigned* src = g_xbits + ((size_t)(b * NPIX + gh * Ww)) * CW;
            unsigned* dst = &sx[r][1][0];
            for (int i = tid; i < Ww * CW; i += 512) dst[i] = src[i];
        }
    }
    __syncthreads();

    // per-thread weights: 9 taps x 4 words (this half)
    unsigned wreg[36];
    {
        const unsigned* wp = g_wbits + co * 72 + half * 4;
#pragma unroll
        for (int t = 0; t < 9; t++) {
            uint4 q = *(const uint4*)(wp + t * CW);
            wreg[t * 4 + 0] = q.x; wreg[t * 4 + 1] = q.y;
            wreg[t * 4 + 2] = q.z; wreg[t * 4 + 3] = q.w;
        }
    }
    // per-tap weight popcounts (this half) for border corrections
    int nw[9];
#pragma unroll
    for (int t = 0; t < 9; t++)
        nw[t] = __popc(wreg[t*4]) + __popc(wreg[t*4+1]) + __popc(wreg[t*4+2]) + __popc(wreg[t*4+3]);

    int nwc0 = nw[0] + nw[3] + nw[6];
    int nwc2 = nw[2] + nw[5] + nw[8];

    // row A (h0): only possible invalid row is tap-row 0 (h0==0)
    int rflagA = (h0 == 0) ? 1 : 0;
    int nvA    = rflagA ? 6 : 9;
    int corrA  = rflagA ? (nw[0] + nw[1] + nw[2]) : 0;
    int cornA  = rflagA ? nw[0] : 0;     // corner tap for w=0
    int cornA2 = rflagA ? nw[2] : 0;     // corner tap for w=55
    // row B (h1): only possible invalid row is tap-row 2 (h1==55)
    int rflagB = (h1 == Hh - 1) ? 1 : 0;
    int nvB    = rflagB ? 6 : 9;
    int corrB  = rflagB ? (nw[6] + nw[7] + nw[8]) : 0;
    int cornB  = rflagB ? nw[6] : 0;     // corner tap for w=0
    int cornB2 = rflagB ? nw[8] : 0;     // corner tap for w=55

    short* soutA = g_S + ((size_t)(b * NPIX) + h0 * Ww) * COUT + co;
    short* soutB = g_S + ((size_t)(b * NPIX) + h1 * Ww) * COUT + co;
    int lsum = 0, lsq = 0;

    // compute P for both rows at window position w (L0 CSA + direct popc)
    auto computeP2 = [&](int w, int& PA, int& PB) {
        int p1A = 0, p2A = 0, p1B = 0, p2B = 0;
#pragma unroll
        for (int c = 0; c < 3; c++) {
            uint4 x0 = *(const uint4*)(&sx[0][w + c][half * 4]);
            uint4 x1 = *(const uint4*)(&sx[1][w + c][half * 4]);
            uint4 x2 = *(const uint4*)(&sx[2][w + c][half * 4]);
            uint4 x3 = *(const uint4*)(&sx[3][w + c][half * 4]);
            unsigned r0[4] = {x0.x, x0.y, x0.z, x0.w};
            unsigned r1[4] = {x1.x, x1.y, x1.z, x1.w};
            unsigned r2[4] = {x2.x, x2.y, x2.z, x2.w};
            unsigned r3[4] = {x3.x, x3.y, x3.z, x3.w};
#pragma unroll
            for (int j = 0; j < 4; j++) {
                unsigned w0 = wreg[(0 * 3 + c) * 4 + j];
                unsigned w1 = wreg[(1 * 3 + c) * 4 + j];
                unsigned w2 = wreg[(2 * 3 + c) * 4 + j];
                unsigned sA, cA, sB, cB;
                csa(r0[j] ^ w0, r1[j] ^ w1, r2[j] ^ w2, sA, cA);
                csa(r1[j] ^ w0, r2[j] ^ w1, r3[j] ^ w2, sB, cB);
                p1A += __popc(sA); p2A += __popc(cA);
                p1B += __popc(sB); p2B += __popc(cB);
            }
        }
        PA = p1A + 2 * p2A;
        PB = p1B + 2 * p2B;
    };

    auto emit = [&](int w, int nvalA, int corA, int nvalB, int corB) {
        int PA, PB;
        computeP2(w, PA, PB);
        int ShA = 128 * nvalA - 2 * PA + 2 * corA;
        int ShB = 128 * nvalB - 2 * PB + 2 * corB;
        int SA = ShA + __shfl_xor_sync(0xffffffffu, ShA, 1);
        int SB = ShB + __shfl_xor_sync(0xffffffffu, ShB, 1);
        if (half == 0) {
            soutA[(size_t)w * COUT] = (short)SA;
            soutB[(size_t)w * COUT] = (short)SB;
            lsum += SA + SB;
            lsq  += SA * SA + SB * SB;   // <= 112*2304^2 = 5.9e8 < INT_MAX
        }
    };

    // peel borders; border column: nvalid = nv - 3 + rflag (corner overlap)
    emit(0,      nvA - 3 + rflagA, corrA + nwc0 - cornA,
                 nvB - 3 + rflagB, corrB + nwc0 - cornB);
#pragma unroll 3
    for (int w = 1; w < Ww - 1; w++) emit(w, nvA, corrA, nvB, corrB);
    emit(Ww - 1, nvA - 3 + rflagA, corrA + nwc2 - cornA2,
                 nvB - 3 + rflagB, corrB + nwc2 - cornB2);

    if (half == 0) {
        atomicAdd(&g_sum[co], lsum);
        atomicAdd(&g_sumsq[co], (unsigned long long)(long long)lsq);
    }
}

// ----------------- kernel 5: finalize per-channel thresholds -----------------
__global__ void finalize_kernel(const float* __restrict__ gamma,
                                const float* __restrict__ beta) {
    int co = threadIdx.x;
    if (co >= COUT) return;
    double s    = (double)g_sum[co];
    double sq   = (double)(long long)g_sumsq[co];
    double mean = s / NVALS;
    double var  = sq / NVALS - mean * mean;            // exact var of integer S
    double a    = (double)g_alpha[co];
    double inv  = 1.0 / sqrt(a * a * var + BN_EPS);
    double sc   = (double)gamma[co] * a * inv;
    g_scale[co] = (float)sc;
    g_shift[co] = (float)((double)beta[co] - sc * mean);
}

// ----------------- kernel 6: threshold + transpose [b][p][co] -> [b][co][p] -----------------
__global__ void __launch_bounds__(256) thresh_kernel(float* __restrict__ out) {
    __shared__ float tile[32][33];
    int p0  = blockIdx.x * 32;     // 98 tiles (3136 = 98*32)
    int co0 = blockIdx.y * 32;     // 8 tiles
    int b   = blockIdx.z;
    int tx  = threadIdx.x;         // 0..31
    int ty  = threadIdx.y;         // 0..7

    float sc = g_scale[co0 + tx];
    float sh = g_shift[co0 + tx];
#pragma unroll
    for (int r = 0; r < 4; r++) {
        int pl = ty * 4 + r;
        short s = g_S[((size_t)(b * NPIX + p0 + pl)) * COUT + co0 + tx];
        tile[pl][tx] = (fmaf(sc, (float)s, sh) > 0.0f) ? 1.0f : 0.0f;
    }
    __syncthreads();
#pragma unroll
    for (int r = 0; r < 4; r++) {
        int cl = ty * 4 + r;
        out[((size_t)(b * COUT + co0 + cl)) * NPIX + p0 + tx] = tile[tx][cl];
    }
}

// ----------------- launch -----------------
extern "C" void kernel_launch(void* const* d_in, const int* in_sizes, int n_in,
                              void* d_out, int out_size) {
    const float* x      = (const float*)d_in[0];
    const float* weight = (const float*)d_in[1];
    // const float* bias = (const float*)d_in[2];  // cancels inside BN; unused
    const float* gamma  = (const float*)d_in[3];
    const float* beta   = (const float*)d_in[4];
    float* out = (float*)d_out;

    zero_stats_kernel<<<1, 256>>>();
    prep_w_kernel<<<COUT, 256>>>(weight);
    {
        int nthreads = BATCH * CW * (NPIX / 4);
        binarize_kernel<<<(nthreads + 255) / 256, 256>>>(x);
    }
    conv_kernel<<<dim3(Hh / 2, BATCH), 512>>>();
    finalize_kernel<<<1, 256>>>(gamma, beta);
    thresh_kernel<<<dim3(NPIX / 32, COUT / 32, BATCH), dim3(32, 8)>>>(out);
}